// round 15
// baseline (speedup 1.0000x reference)
#include <cuda_runtime.h>
#include <cuda_bf16.h>
#include <cstdint>

#define L      2048
#define DM     512
#define DI     1024
#define NST    16
#define NC     64           // scan chunks
#define TCH    (L / NC)     // 32 steps per chunk

// ------------------------- scratch (__device__ globals, no alloc) ----------
__device__ float g_xz[2][L * 2 * DI];        // in-proj output per dir
__device__ float g_xc[2][L * DI];            // conv output
__device__ float g_sxc[2][L * DI];           // silu(conv) [tf32-rounded]
__device__ float g_BCp[2][L * 128];          // padded BC: [l][0..15]=B, [16..31]=C
__device__ float g_dt[2][L * DI];            // softplus
__device__ float g_uu[L * 2 * DI];           // [l][u0 | u1rev] tf32-rounded
__device__ float g_aprod[2][NC * DI * NST];  // [c][s][d]
__device__ float g_hpart[2][NC * DI * NST];
__device__ float g_hinit[2][NC * DI * NST];
__device__ float g_wpp[DM * 2 * DI];         // W''^T [512][2048]
__device__ float g_w3[2][DI * DI];           // W3^T  [1024][1024] per dir
__device__ float g_bpp[DM];                  // fused fusion bias
__device__ float g_b3[2][DI];                // fused dt bias
__device__ float g_bcb[2][128];              // BC bias padded (cols 32.. stay 0)
__device__ float g_zero[1024];               // zero bias

// transposed/rounded weights only (x, xpW, outW read raw -> HW tf32 trunc)
#define OFF_INWT0  0
#define OFF_INWT1  (OFF_INWT0 + 2 * DI * DM)
#define OFF_DTWT0  (OFF_INWT1 + 2 * DI * DM)
#define OFF_DTWT1  (OFF_DTWT0 + DI * DI)
#define OFF_FUWT   (OFF_DTWT1 + DI * DI)
#define OFF_XPBCT0 (OFF_FUWT  + DM * 2 * DM)  // [128][1024], rows 32.. stay 0
#define OFF_XPBCT1 (OFF_XPBCT0 + 128 * DI)
#define WR_TOTAL   (OFF_XPBCT1 + 128 * DI)
__device__ float g_wr[WR_TOTAL];

// ------------------------- helpers -----------------------------------------
__device__ __forceinline__ uint32_t f2t(float f) {
    uint32_t u;
    asm("cvt.rna.tf32.f32 %0, %1;" : "=r"(u) : "f"(f));
    return u;
}
__device__ __forceinline__ uint32_t smem_u32(const void* p) {
    return (uint32_t)__cvta_generic_to_shared(p);
}
__device__ __forceinline__ void mma_tf32(float* c, const uint32_t* a, const uint32_t* b) {
    asm volatile(
        "mma.sync.aligned.m16n8k8.row.col.f32.tf32.tf32.f32 "
        "{%0,%1,%2,%3}, {%4,%5,%6,%7}, {%8,%9}, {%0,%1,%2,%3};\n"
        : "+f"(c[0]), "+f"(c[1]), "+f"(c[2]), "+f"(c[3])
        : "r"(a[0]), "r"(a[1]), "r"(a[2]), "r"(a[3]), "r"(b[0]), "r"(b[1]));
}
__device__ __forceinline__ void ldsm4(uint32_t* r, uint32_t a) {
    asm volatile("ldmatrix.sync.aligned.m8n8.x4.shared.b16 {%0,%1,%2,%3}, [%4];"
        : "=r"(r[0]), "=r"(r[1]), "=r"(r[2]), "=r"(r[3]) : "r"(a));
}
__device__ __forceinline__ void cpa16(uint32_t s, const void* g) {
    asm volatile("cp.async.cg.shared.global [%0], [%1], 16;" :: "r"(s), "l"(g));
}
#define CPA_COMMIT()  asm volatile("cp.async.commit_group;" ::: "memory")
#define CPA_WAIT(n)   asm volatile("cp.async.wait_group %0;" :: "n"(n) : "memory")
__device__ __forceinline__ void redg_add(float* p, float v) {
    asm volatile("red.global.add.f32 [%0], %1;" :: "l"(p), "f"(v) : "memory");
}

// ------------------------- prep kernel (weight transposes) -----------------
struct PrepArgs {
    const float* ts[5]; float* td[5]; int tK[5], tN[5], tld[5], tcoff[5];
};

__global__ void prep_kernel(PrepArgs pa)
{
    const int m = blockIdx.z;
    const int K = pa.tK[m], N = pa.tN[m], ld = pa.tld[m], coff = pa.tcoff[m];
    const int nx = N >> 5;
    const int tile = blockIdx.x;
    if (tile >= nx * (K >> 5)) return;
    const int n0 = (tile % nx) * 32, k0 = (tile / nx) * 32;
    __shared__ float t[32][33];
    const int tx = threadIdx.x & 31, ty = threadIdx.x >> 5;
    const float* s = pa.ts[m];
    #pragma unroll
    for (int j = 0; j < 32; j += 8)
        t[ty + j][tx] = s[(size_t)(k0 + ty + j) * ld + coff + n0 + tx];
    __syncthreads();
    float* d = pa.td[m];
    #pragma unroll
    for (int j = 0; j < 32; j += 8)
        d[(size_t)(n0 + ty + j) * K + k0 + tx] = __uint_as_float(f2t(t[tx][ty + j]));
}

// ------------------------- bias chain (side stream) ------------------------
__global__ void biascopy_kernel(const float* __restrict__ fub,
                                const float* __restrict__ dtb0,
                                const float* __restrict__ dtb1,
                                const float* __restrict__ xpb0,
                                const float* __restrict__ xpb1)
{
    const int i = blockIdx.x * 256 + threadIdx.x;
    if (i < DM)                   g_bpp[i] = fub[i];
    else if (i < DM + DI)         g_b3[0][i - DM] = dtb0[i - DM];
    else if (i < DM + 2 * DI)     g_b3[1][i - DM - DI] = dtb1[i - DM - DI];
    else if (i < DM + 2 * DI + 32)      g_bcb[0][i - DM - 2 * DI] = xpb0[DI + i - DM - 2 * DI];
    else if (i < DM + 2 * DI + 64)      g_bcb[1][i - DM - 2 * DI - 32] = xpb1[DI + i - DM - 2 * DI - 32];
}

// bias partials: z=0 bpp, z=1/2 b3[dir]
__global__ void partials_kernel(const float* __restrict__ fuW,
                                const float* __restrict__ ob0,
                                const float* __restrict__ ob1,
                                const float* __restrict__ dtW0,
                                const float* __restrict__ dtW1,
                                const float* __restrict__ xpb0,
                                const float* __restrict__ xpb1)
{
    const int z = blockIdx.z;
    if (z == 0) {
        if (blockIdx.x >= 4) return;
        const int n = blockIdx.x * 128 + threadIdx.x;
        const int j0 = blockIdx.y * 16;
        float acc = 0.f;
        #pragma unroll
        for (int j = j0; j < j0 + 16; j++) {
            acc += ob0[j] * fuW[(size_t)j * DM + n];
            acc += ob1[j] * fuW[(size_t)(512 + j) * DM + n];
        }
        redg_add(&g_bpp[n], acc);
    } else {
        const int dir = z - 1;
        const float* dtW = dir ? dtW1 : dtW0;
        const float* xpb = dir ? xpb1 : xpb0;
        const int n = blockIdx.x * 128 + threadIdx.x;
        const int j0 = blockIdx.y * 32;
        float acc = 0.f;
        #pragma unroll
        for (int j = j0; j < j0 + 32; j++)
            acc += xpb[j] * dtW[(size_t)j * DI + n];
        redg_add(&g_b3[dir][n], acc);
    }
}

__global__ void initout_kernel(float* __restrict__ out)
{
    const int i = (blockIdx.x * 256 + threadIdx.x) * 4;
    *(float4*)(out + i) = *(const float4*)&g_bpp[i & (DM - 1)];
}

// ------------------------- multi-task ldmatrix tf32 GEMM -------------------
// 256 threads, 8 warps (2x4), warp tile 64x32, CTA tile 128x128, 3 stages.
// epi: 0=none, 1=softplus, 2=round-to-tf32, 3=red.add (no bias)
struct GTask {
    const float *A, *B, *bias; float* C;
    int revA, revC, colOff, lda, ldb, ldc, M, K, k00, epi, nbx;
};
struct GMulti { GTask t[6]; int start[7]; int nt; };

#define TL_STAGE  32768                 // A 16KB + B 16KB (bytes)
#define TL_SMEM   (3 * TL_STAGE)        // 98304

__global__ __launch_bounds__(256, 2)
void tgemm_multi(GMulti gm)
{
    extern __shared__ float smem[];
    const uint32_t sb = smem_u32(smem);
    const int tid = threadIdx.x;
    const int lane = tid & 31;
    const int warp = tid >> 5;
    const int wm = warp & 1;
    const int wn = warp >> 1;
    const int g  = lane >> 2;
    const int cc = lane & 3;

    int ti = 0;
    {
        const int b = blockIdx.x;
        while (ti + 1 < gm.nt && b >= gm.start[ti + 1]) ti++;
    }
    const GTask t = gm.t[ti];
    const int local = blockIdx.x - gm.start[ti];
    const int bx = local % t.nbx;
    const int by = local / t.nbx;

    const float* A = t.A;
    const float* B = t.B;
    const int lda = t.lda, ldb = t.ldb, M = t.M, K = t.K, k00 = t.k00;

    // ---- cp.async mapping: 4 A-chunks + 4 B-chunks of 16B per thread ----
    const int rr = tid >> 3;            // 0..31
    const int kq = tid & 7;             // 0..7
    const float* aBase;
    long aStep;
    {
        long r0 = by * 128 + rr;
        if (t.revA) { aBase = A + (size_t)(M - 1 - r0) * lda; aStep = -32L * lda; }
        else        { aBase = A + (size_t)r0 * lda;           aStep =  32L * lda; }
        aBase += k00 + kq * 4;
    }
    const float* bBase = B + (size_t)(bx * 128 + rr) * ldb + k00 + kq * 4;
    const long bStep = 32L * ldb;
    const uint32_t dA0 = rr * 128 + ((kq * 16) ^ ((rr & 7) * 16));

    auto issue = [&](int k0, int st) {
        const uint32_t base = sb + st * TL_STAGE;
        #pragma unroll
        for (int j = 0; j < 4; j++) cpa16(base + dA0 + j * 4096, aBase + k0 + j * aStep);
        #pragma unroll
        for (int j = 0; j < 4; j++) cpa16(base + 16384 + dA0 + j * 4096, bBase + k0 + j * bStep);
        CPA_COMMIT();
    };

    // ---- ldmatrix lane constants ----
    const uint32_t lxor   = (lane & 7) << 4;
    const uint32_t la_row = (lane & 7) + ((lane >> 3) & 1) * 8;
    const uint32_t la_k16 = (lane >> 4) << 4;
    const uint32_t lb_row = (lane & 7) + ((lane >> 4) << 3);
    const uint32_t lb_k16 = ((lane >> 3) & 1) << 4;
    uint32_t rowAoff[4], rowBoff[2];
    #pragma unroll
    for (int mt = 0; mt < 4; mt++) rowAoff[mt] = (wm * 64 + mt * 16 + la_row) * 128;
    #pragma unroll
    for (int np = 0; np < 2; np++) rowBoff[np] = 16384 + (wn * 32 + np * 16 + lb_row) * 128;

    float acc[4][4][4];
    #pragma unroll
    for (int mt = 0; mt < 4; mt++)
        #pragma unroll
        for (int nt = 0; nt < 4; nt++)
            #pragma unroll
            for (int i = 0; i < 4; i++) acc[mt][nt][i] = 0.f;

    const int nIt = K / 32;
    issue(0, 0);
    issue(32, 1);

    int st = 0, ist = 2;
    for (int it = 0; it < nIt; ++it) {
        if (it + 2 < nIt) { CPA_WAIT(1); } else { CPA_WAIT(0); }
        __syncthreads();
        if (it + 2 < nIt) {
            issue((it + 2) * 32, ist);
            if (++ist == 3) ist = 0;
        }
        const uint32_t stb = sb + st * TL_STAGE;
        if (++st == 3) st = 0;

        #pragma unroll
        for (int ks = 0; ks < 4; ks++) {
            const uint32_t ksb = ks * 32;
            uint32_t a[4][4], b[4][2];
            #pragma unroll
            for (int mt = 0; mt < 4; mt++)
                ldsm4(a[mt], stb + rowAoff[mt] + ((ksb + la_k16) ^ lxor));
            #pragma unroll
            for (int np = 0; np < 2; np++)
                ldsm4(&b[2 * np][0], stb + rowBoff[np] + ((ksb + lb_k16) ^ lxor));
            #pragma unroll
            for (int mt = 0; mt < 4; mt++)
                #pragma unroll
                for (int nt = 0; nt < 4; nt++)
                    mma_tf32(acc[mt][nt], a[mt], b[nt]);
        }
    }

    // ---- epilogue ----
    #pragma unroll
    for (int mt = 0; mt < 4; mt++) {
        int r0 = by * 128 + wm * 64 + mt * 16 + g;
        int r1 = r0 + 8;
        int or0 = t.revC ? (M - 1 - r0) : r0;
        int or1 = t.revC ? (M - 1 - r1) : r1;
        float* crow0 = t.C + (size_t)or0 * t.ldc + t.colOff;
        float* crow1 = t.C + (size_t)or1 * t.ldc + t.colOff;
        #pragma unroll
        for (int nt = 0; nt < 4; nt++) {
            const int col = bx * 128 + wn * 32 + nt * 8 + 2 * cc;
            if (t.epi == 3) {
                redg_add(&crow0[col],     acc[mt][nt][0]);
                redg_add(&crow0[col + 1], acc[mt][nt][1]);
                redg_add(&crow1[col],     acc[mt][nt][2]);
                redg_add(&crow1[col + 1], acc[mt][nt][3]);
            } else {
                float b0 = t.bias[col], b1 = t.bias[col + 1];
                float v00 = acc[mt][nt][0] + b0, v01 = acc[mt][nt][1] + b1;
                float v10 = acc[mt][nt][2] + b0, v11 = acc[mt][nt][3] + b1;
                if (t.epi == 1) {
                    v00 = (v00 > 15.f) ? v00 : log1pf(__expf(v00));
                    v01 = (v01 > 15.f) ? v01 : log1pf(__expf(v01));
                    v10 = (v10 > 15.f) ? v10 : log1pf(__expf(v10));
                    v11 = (v11 > 15.f) ? v11 : log1pf(__expf(v11));
                } else if (t.epi == 2) {
                    v00 = __uint_as_float(f2t(v00)); v01 = __uint_as_float(f2t(v01));
                    v10 = __uint_as_float(f2t(v10)); v11 = __uint_as_float(f2t(v11));
                }
                *(float2*)&crow0[col] = make_float2(v00, v01);
                *(float2*)&crow1[col] = make_float2(v10, v11);
            }
        }
    }
}

// ------------------------- causal depthwise conv (K=4) + silu, float4 ------
__global__ void conv_silu_kernel(const float* __restrict__ cw_f,
                                 const float* __restrict__ cb_f,
                                 const float* __restrict__ cw_b,
                                 const float* __restrict__ cb_b)
{
    const int dir = blockIdx.z;
    const int idx4 = (blockIdx.x * blockDim.x + threadIdx.x) * 4;
    const int l = idx4 >> 10;
    const int d0 = idx4 & (DI - 1);
    const float* xz = g_xz[dir];
    const float* w = dir ? cw_b : cw_f;
    const float* b = dir ? cb_b : cb_f;
    float wk[4][4];
    #pragma unroll
    for (int j = 0; j < 4; j++)
        *(float4*)wk[j] = *(const float4*)&w[(d0 + j) * 4];
    float4 bv = *(const float4*)&b[d0];
    float s[4] = { bv.x, bv.y, bv.z, bv.w };
    #pragma unroll
    for (int k = 0; k < 4; k++) {
        int ls = l - 3 + k;
        if (ls >= 0) {
            float4 xv = *(const float4*)&xz[(size_t)ls * (2 * DI) + d0];
            s[0] += xv.x * wk[0][k];
            s[1] += xv.y * wk[1][k];
            s[2] += xv.z * wk[2][k];
            s[3] += xv.w * wk[3][k];
        }
    }
    *(float4*)&g_xc[dir][idx4] = make_float4(s[0], s[1], s[2], s[3]);
    float4 o;
    o.x = __uint_as_float(f2t(s[0] / (1.f + __expf(-s[0]))));
    o.y = __uint_as_float(f2t(s[1] / (1.f + __expf(-s[1]))));
    o.z = __uint_as_float(f2t(s[2] / (1.f + __expf(-s[2]))));
    o.w = __uint_as_float(f2t(s[3] / (1.f + __expf(-s[3]))));
    *(float4*)&g_sxc[dir][idx4] = o;
}

// ------------------------- chunked scan (s-in-thread, 2 ch/thread) ---------
#define LOG2E 1.44269504088896f

__global__ __launch_bounds__(256)
void scan_phaseA(const float* __restrict__ A_log)
{
    __shared__ float sB[TCH][16];
    const int dir = blockIdx.z;
    const int c = blockIdx.x;
    const int d0 = blockIdx.y * 512 + threadIdx.x * 2;
    const float* bc = g_BCp[dir];
    for (int i = threadIdx.x; i < TCH * 16; i += 256) {
        const int t = i >> 4, s = i & 15;
        sB[t][s] = bc[(c * TCH + t) * 128 + s];
    }
    __syncthreads();

    float2 Av[NST];
    #pragma unroll
    for (int q = 0; q < 4; q++) {
        float4 v0 = *(const float4*)&A_log[d0 * NST + q * 4];
        float4 v1 = *(const float4*)&A_log[(d0 + 1) * NST + q * 4];
        Av[q * 4 + 0] = make_float2(-__expf(v0.x) * LOG2E, -__expf(v1.x) * LOG2E);
        Av[q * 4 + 1] = make_float2(-__expf(v0.y) * LOG2E, -__expf(v1.y) * LOG2E);
        Av[q * 4 + 2] = make_float2(-__expf(v0.z) * LOG2E, -__expf(v1.z) * LOG2E);
        Av[q * 4 + 3] = make_float2(-__expf(v0.w) * LOG2E, -__expf(v1.w) * LOG2E);
    }
    float2 h[NST], ap[NST];
    #pragma unroll
    for (int s = 0; s < NST; s++) {
        h[s] = make_float2(0.f, 0.f);
        ap[s] = make_float2(1.f, 1.f);
    }

    const float* dtp = g_dt[dir];
    const float* xp = g_xc[dir];
    int l = c * TCH;
    for (int t = 0; t < TCH; t++, l++) {
        const float2 dtv = *(const float2*)&dtp[l * DI + d0];
        const float2 xv  = *(const float2*)&xp[l * DI + d0];
        const float dtx0 = dtv.x * xv.x, dtx1 = dtv.y * xv.y;
        #pragma unroll
        for (int s = 0; s < NST; s++) {
            const float a0 = exp2f(dtv.x * Av[s].x);
            const float a1 = exp2f(dtv.y * Av[s].y);
            const float Bs = sB[t][s];
            h[s].x = a0 * h[s].x + dtx0 * Bs;
            h[s].y = a1 * h[s].y + dtx1 * Bs;
            ap[s].x *= a0; ap[s].y *= a1;
        }
    }
    const int ob = (c << 14) + d0;
    #pragma unroll
    for (int s = 0; s < NST; s++) {
        *(float2*)&g_aprod[dir][ob + (s << 10)] = ap[s];
        *(float2*)&g_hpart[dir][ob + (s << 10)] = h[s];
    }
}

__global__ void scan_phaseB()
{
    const int idx = blockIdx.x * blockDim.x + threadIdx.x;
    const int dir = idx >> 14;
    const int ds = idx & 16383;
    float h = 0.f;
    float ap = g_aprod[dir][ds];
    float hp = g_hpart[dir][ds];
    for (int c = 0; c < NC; c++) {
        float apn = 0.f, hpn = 0.f;
        if (c + 1 < NC) {
            const int on = ((c + 1) << 14) + ds;
            apn = g_aprod[dir][on];
            hpn = g_hpart[dir][on];
        }
        g_hinit[dir][(c << 14) + ds] = h;
        h = ap * h + hp;
        ap = apn; hp = hpn;
    }
}

__global__ __launch_bounds__(256)
void scan_phaseC(const float* __restrict__ A_log,
                 const float* __restrict__ Dp)
{
    __shared__ float sBC[TCH][32];
    const int dir = blockIdx.z;
    const int c = blockIdx.x;
    const int d0 = blockIdx.y * 512 + threadIdx.x * 2;
    const float* bc = g_BCp[dir];
    for (int i = threadIdx.x; i < TCH * 32; i += 256) {
        const int t = i >> 5, s = i & 31;
        sBC[t][s] = bc[(c * TCH + t) * 128 + s];
    }
    __syncthreads();

    float2 Av[NST];
    #pragma unroll
    for (int q = 0; q < 4; q++) {
        float4 v0 = *(const float4*)&A_log[d0 * NST + q * 4];
        float4 v1 = *(const float4*)&A_log[(d0 + 1) * NST + q * 4];
        Av[q * 4 + 0] = make_float2(-__expf(v0.x) * LOG2E, -__expf(v1.x) * LOG2E);
        Av[q * 4 + 1] = make_float2(-__expf(v0.y) * LOG2E, -__expf(v1.y) * LOG2E);
        Av[q * 4 + 2] = make_float2(-__expf(v0.z) * LOG2E, -__expf(v1.z) * LOG2E);
        Av[q * 4 + 3] = make_float2(-__expf(v0.w) * LOG2E, -__expf(v1.w) * LOG2E);
    }
    const float2 Dv = *(const float2*)&Dp[d0];
    float2 h[NST];
    {
        const int ob = (c << 14) + d0;
        #pragma unroll
        for (int s = 0; s < NST; s++)
            h[s] = *(const float2*)&g_hinit[dir][ob + (s << 10)];
    }

    const float* dtp = g_dt[dir];
    const float* xp = g_xc[dir];
    const float* xz = g_xz[dir];
    int l = c * TCH;
    for (int t = 0; t < TCH; t++, l++) {
        const float2 dtv = *(const float2*)&dtp[l * DI + d0];
        const float2 xv  = *(const float2*)&xp[l * DI + d0];
        const float2 zv  = *(const float2*)&xz[(size_t)l * (2 * DI) + DI + d0];
        const float dtx0 = dtv.x * xv.x, dtx1 = dtv.y * xv.y;
        float y0 = Dv.x * xv.x, y1 = Dv.y * xv.y;
        #pragma unroll
        for (int s = 0; s < NST; s++) {
            const float a0 = exp2f(dtv.x * Av[s].x);
            const float a1 = exp2f(dtv.y * Av[s].y);
            const float Bs = sBC[t][s];
            const float Cs = sBC[t][16 + s];
            h[s].x = a0 * h[s].x + dtx0 * Bs;
            h[s].y = a1 * h[s].y + dtx1 * Bs;
            y0 += h[s].x * Cs;
            y1 += h[s].y * Cs;
        }
        const float u0 = y0 * (zv.x / (1.f + __expf(-zv.x)));
        const float u1 = y1 * (zv.y / (1.f + __expf(-zv.y)));
        const size_t row = dir ? (size_t)(L - 1 - l) : (size_t)l;
        float2 uo = make_float2(__uint_as_float(f2t(u0)), __uint_as_float(f2t(u1)));
        *(float2*)&g_uu[row * (2 * DI) + dir * DI + d0] = uo;
    }
}

// ------------------------- host launcher --------------------------------
extern "C" void kernel_launch(void* const* d_in, const int* in_sizes, int n_in,
                              void* d_out, int out_size)
{
    (void)in_sizes; (void)n_in; (void)out_size;
    const float* x = (const float*)d_in[0];
    const float* inW[2]  = { (const float*)d_in[1],  (const float*)d_in[11] };
    const float* inb[2]  = { (const float*)d_in[2],  (const float*)d_in[12] };
    const float* cw[2]   = { (const float*)d_in[3],  (const float*)d_in[13] };
    const float* cb[2]   = { (const float*)d_in[4],  (const float*)d_in[14] };
    const float* xpW[2]  = { (const float*)d_in[5],  (const float*)d_in[15] };
    const float* xpb[2]  = { (const float*)d_in[6],  (const float*)d_in[16] };
    const float* dtW[2]  = { (const float*)d_in[7],  (const float*)d_in[17] };
    const float* dtb[2]  = { (const float*)d_in[8],  (const float*)d_in[18] };
    const float* outW[2] = { (const float*)d_in[9],  (const float*)d_in[19] };
    const float* outb[2] = { (const float*)d_in[10], (const float*)d_in[20] };
    const float* A_log   = (const float*)d_in[21];
    const float* Dp      = (const float*)d_in[22];
    const float* fuW     = (const float*)d_in[23];
    const float* fub     = (const float*)d_in[24];
    float* out = (float*)d_out;

    float *xz, *uu, *wr, *sxc, *dtbuf, *wpp, *w3, *b3, *zero, *bcp, *bcb;
    cudaGetSymbolAddress((void**)&xz,    g_xz);
    cudaGetSymbolAddress((void**)&uu,    g_uu);
    cudaGetSymbolAddress((void**)&wr,    g_wr);
    cudaGetSymbolAddress((void**)&sxc,   g_sxc);
    cudaGetSymbolAddress((void**)&dtbuf, g_dt);
    cudaGetSymbolAddress((void**)&wpp,   g_wpp);
    cudaGetSymbolAddress((void**)&w3,    g_w3);
    cudaGetSymbolAddress((void**)&b3,    g_b3);
    cudaGetSymbolAddress((void**)&zero,  g_zero);
    cudaGetSymbolAddress((void**)&bcp,   g_BCp);
    cudaGetSymbolAddress((void**)&bcb,   g_bcb);

    cudaFuncSetAttribute(tgemm_multi, cudaFuncAttributeMaxDynamicSharedMemorySize, TL_SMEM);

    const dim3 blk(256);

    // side stream + fork/join events
    cudaStream_t side;
    cudaStreamCreateWithFlags(&side, cudaStreamNonBlocking);
    cudaEvent_t evFork, evJoin;
    cudaEventCreateWithFlags(&evFork, cudaEventDisableTiming);
    cudaEventCreateWithFlags(&evJoin, cudaEventDisableTiming);

    cudaEventRecord(evFork, 0);
    cudaStreamWaitEvent(side, evFork, 0);

    // ---- side branch: biases + remaining transposes + compose GEMMs ----
    biascopy_kernel<<<11, blk, 0, side>>>(fub, dtb[0], dtb[1], xpb[0], xpb[1]);
    partials_kernel<<<dim3(8, 32, 3), 128, 0, side>>>(fuW, outb[0], outb[1],
                                                      dtW[0], dtW[1], xpb[0], xpb[1]);
    initout_kernel<<<L * DM / 4 / 256, blk, 0, side>>>(out);
    {
        PrepArgs pa{};
        pa.ts[0] = dtW[0]; pa.td[0] = wr + OFF_DTWT0;  pa.tK[0] = DI;     pa.tN[0] = DI; pa.tld[0] = DI;   pa.tcoff[0] = 0;
        pa.ts[1] = dtW[1]; pa.td[1] = wr + OFF_DTWT1;  pa.tK[1] = DI;     pa.tN[1] = DI; pa.tld[1] = DI;   pa.tcoff[1] = 0;
        pa.ts[2] = fuW;    pa.td[2] = wr + OFF_FUWT;   pa.tK[2] = 2 * DM; pa.tN[2] = DM; pa.tld[2] = DM;   pa.tcoff[2] = 0;
        pa.ts[3] = xpW[0]; pa.td[3] = wr + OFF_XPBCT0; pa.tK[3] = DI;     pa.tN[3] = 32; pa.tld[3] = 1056; pa.tcoff[3] = DI;
        pa.ts[4] = xpW[1]; pa.td[4] = wr + OFF_XPBCT1; pa.tK[4] = DI;     pa.tN[4] = 32; pa.tld[4] = 1056; pa.tcoff[4] = DI;
        prep_kernel<<<dim3(1024, 1, 5), blk, 0, side>>>(pa);
    }
    {   // compose mega: W3 x2 (K=1056) + Wpp x2
        GMulti gm{};
        int s = 0, i = 0;
        for (int d2 = 0; d2 < 2; d2++) {
            gm.t[i] = { wr + (d2 ? OFF_DTWT1 : OFF_DTWT0), xpW[d2], zero,
                        w3 + (size_t)d2 * DI * DI,
                        0, 0, 0, DI, 1056, DI, DI, DI, 0, 2, 8 };
            gm.start[i] = s; s += 8 * 8; i++;
        }
        for (int d2 = 0; d2 < 2; d2++) {
            gm.t[i] = { wr + OFF_FUWT + d2 * 512, outW[d2], zero,
                        wpp,
                        0, 0, d2 * DI, 2 * DM, DM, 2 * DI, DM, DM, 0, 2, 8 };
            gm.start[i] = s; s += 8 * 4; i++;
        }
        gm.start[i] = s; gm.nt = i;
        tgemm_multi<<<s, blk, TL_SMEM, side>>>(gm);
    }
    cudaEventRecord(evJoin, side);

    // ---- main branch ----
    // 1. prep: in-proj weight transposes only
    {
        PrepArgs pa{};
        pa.ts[0] = inW[0]; pa.td[0] = wr + OFF_INWT0; pa.tK[0] = DM; pa.tN[0] = 2 * DI; pa.tld[0] = 2 * DI; pa.tcoff[0] = 0;
        pa.ts[1] = inW[1]; pa.td[1] = wr + OFF_INWT1; pa.tK[1] = DM; pa.tN[1] = 2 * DI; pa.tld[1] = 2 * DI; pa.tcoff[1] = 0;
        prep_kernel<<<dim3(1024, 1, 2), blk>>>(pa);
    }

    // 2. mega1: in-proj x2 only
    {
        GMulti gm{};
        int s = 0, i = 0;
        for (int d2 = 0; d2 < 2; d2++) {
            gm.t[i] = { x, wr + (d2 ? OFF_INWT1 : OFF_INWT0), inb[d2],
                        xz + (size_t)d2 * L * 2 * DI,
                        d2, 0, 0, DM, DM, 2 * DI, L, DM, 0, 0, 16 };
            gm.start[i] = s; s += 16 * 16; i++;
        }
        gm.start[i] = s; gm.nt = i;
        tgemm_multi<<<s, blk, TL_SMEM>>>(gm);
    }

    // 3. causal conv + silu (overlaps side compose GEMMs)
    conv_silu_kernel<<<dim3(L * DI / 1024, 1, 2), blk>>>(cw[0], cb[0], cw[1], cb[1]);

    // join: mega2 needs W3/b3/bcb/XPBCT; mega3 needs wpp + initout
    cudaStreamWaitEvent(0, evJoin, 0);

    // 4. mega2: dt x2 + BC x2
    {
        GMulti gm{};
        int s = 0, i = 0;
        for (int d2 = 0; d2 < 2; d2++) {
            gm.t[i] = { sxc + (size_t)d2 * L * DI, w3 + (size_t)d2 * DI * DI, b3 + d2 * DI,
                        dtbuf + (size_t)d2 * L * DI,
                        0, 0, 0, DI, DI, DI, L, DI, 0, 1, 8 };
            gm.start[i] = s; s += 8 * 16; i++;
        }
        for (int d2 = 0; d2 < 2; d2++) {
            gm.t[i] = { sxc + (size_t)d2 * L * DI, wr + (d2 ? OFF_XPBCT1 : OFF_XPBCT0), bcb + d2 * 128,
                        bcp + (size_t)d2 * L * 128,
                        0, 0, 0, DI, DI, 128, L, DI, 0, 0, 1 };
            gm.start[i] = s; s += 1 * 16; i++;
        }
        gm.start[i] = s; gm.nt = i;
        tgemm_multi<<<s, blk, TL_SMEM>>>(gm);
    }

    // 5. chunked selective scan -> uu  (2 channels/thread)
    scan_phaseA<<<dim3(NC, DI / 512, 2), blk>>>(A_log);
    scan_phaseB<<<2 * DI * NST / 256, blk>>>();
    scan_phaseC<<<dim3(NC, DI / 512, 2), blk>>>(A_log, Dp);

    // 6. mega3: final fused GEMM out += uu @ W''^T  (split-K=4 via tasks)
    {
        GMulti gm{};
        int s = 0, i = 0;
        for (int kz = 0; kz < 4; kz++) {
            gm.t[i] = { uu, wpp, zero, out,
                        0, 0, 0, 2 * DI, 2 * DI, DM, L, 512, kz * 512, 3, 4 };
            gm.start[i] = s; s += 4 * 16; i++;
        }
        gm.start[i] = s; gm.nt = i;
        tgemm_multi<<<s, blk, TL_SMEM>>>(gm);
    }
}

// round 16
// speedup vs baseline: 1.0255x; 1.0255x over previous
#include <cuda_runtime.h>
#include <cuda_bf16.h>
#include <cstdint>

#define L      2048
#define DM     512
#define DI     1024
#define NST    16
#define NC     64           // scan chunks
#define TCH    (L / NC)     // 32 steps per chunk

// ------------------------- scratch (__device__ globals, no alloc) ----------
__device__ float g_xz[2][L * 2 * DI];        // in-proj output per dir
__device__ float g_xc[2][L * DI];            // conv output
__device__ float g_sxc[2][L * DI];           // silu(conv) [tf32-rounded]
__device__ float g_BCp[2][L * 128];          // padded BC: [l][0..15]=B, [16..31]=C
__device__ float g_dt[2][L * DI];            // softplus
__device__ float g_uu[L * 2 * DI];           // [l][u0 | u1rev] tf32-rounded
__device__ float g_aprod[2][NC * DI * NST];  // [c][s][d]
__device__ float g_hpart[2][NC * DI * NST];
__device__ float g_hinit[2][NC * DI * NST];
__device__ float g_wpp[DM * 2 * DI];         // W''^T [512][2048]
__device__ float g_w3[2][DI * DI];           // W3^T  [1024][1024] per dir
__device__ float g_bpp[DM];                  // fused fusion bias
__device__ float g_b3[2][DI];                // fused dt bias
__device__ float g_bcb[2][128];              // BC bias padded (cols 32.. stay 0)
__device__ float g_zero[1024];               // zero bias

// transposed/rounded weights only (x, xpW, outW read raw -> HW tf32 trunc)
#define OFF_INWT0  0
#define OFF_INWT1  (OFF_INWT0 + 2 * DI * DM)
#define OFF_DTWT0  (OFF_INWT1 + 2 * DI * DM)
#define OFF_DTWT1  (OFF_DTWT0 + DI * DI)
#define OFF_FUWT   (OFF_DTWT1 + DI * DI)
#define OFF_XPBCT0 (OFF_FUWT  + DM * 2 * DM)  // [128][1024], rows 32.. stay 0
#define OFF_XPBCT1 (OFF_XPBCT0 + 128 * DI)
#define WR_TOTAL   (OFF_XPBCT1 + 128 * DI)
__device__ float g_wr[WR_TOTAL];

// ------------------------- helpers -----------------------------------------
__device__ __forceinline__ uint32_t f2t(float f) {
    uint32_t u;
    asm("cvt.rna.tf32.f32 %0, %1;" : "=r"(u) : "f"(f));
    return u;
}
__device__ __forceinline__ uint32_t smem_u32(const void* p) {
    return (uint32_t)__cvta_generic_to_shared(p);
}
__device__ __forceinline__ void mma_tf32(float* c, const uint32_t* a, const uint32_t* b) {
    asm volatile(
        "mma.sync.aligned.m16n8k8.row.col.f32.tf32.tf32.f32 "
        "{%0,%1,%2,%3}, {%4,%5,%6,%7}, {%8,%9}, {%0,%1,%2,%3};\n"
        : "+f"(c[0]), "+f"(c[1]), "+f"(c[2]), "+f"(c[3])
        : "r"(a[0]), "r"(a[1]), "r"(a[2]), "r"(a[3]), "r"(b[0]), "r"(b[1]));
}
__device__ __forceinline__ void ldsm4(uint32_t* r, uint32_t a) {
    asm volatile("ldmatrix.sync.aligned.m8n8.x4.shared.b16 {%0,%1,%2,%3}, [%4];"
        : "=r"(r[0]), "=r"(r[1]), "=r"(r[2]), "=r"(r[3]) : "r"(a));
}
__device__ __forceinline__ void cpa16(uint32_t s, const void* g) {
    asm volatile("cp.async.cg.shared.global [%0], [%1], 16;" :: "r"(s), "l"(g));
}
#define CPA_COMMIT()  asm volatile("cp.async.commit_group;" ::: "memory")
#define CPA_WAIT(n)   asm volatile("cp.async.wait_group %0;" :: "n"(n) : "memory")
__device__ __forceinline__ void redg_add(float* p, float v) {
    asm volatile("red.global.add.f32 [%0], %1;" :: "l"(p), "f"(v) : "memory");
}

// ------------------------- prep kernel (weight transposes only) ------------
struct PrepArgs {
    const float* ts[7]; float* td[7]; int tK[7], tN[7], tld[7], tcoff[7];
};

__global__ void prep_kernel(PrepArgs pa)
{
    const int m = blockIdx.z;
    const int K = pa.tK[m], N = pa.tN[m], ld = pa.tld[m], coff = pa.tcoff[m];
    const int nx = N >> 5;
    const int tile = blockIdx.x;
    if (tile >= nx * (K >> 5)) return;
    const int n0 = (tile % nx) * 32, k0 = (tile / nx) * 32;
    __shared__ float t[32][33];
    const int tx = threadIdx.x & 31, ty = threadIdx.x >> 5;
    const float* s = pa.ts[m];
    #pragma unroll
    for (int j = 0; j < 32; j += 8)
        t[ty + j][tx] = s[(size_t)(k0 + ty + j) * ld + coff + n0 + tx];
    __syncthreads();
    float* d = pa.td[m];
    #pragma unroll
    for (int j = 0; j < 32; j += 8)
        d[(size_t)(n0 + ty + j) * K + k0 + tx] = __uint_as_float(f2t(t[tx][ty + j]));
}

// ------------------------- bias chain (side stream) ------------------------
__global__ void biascopy_kernel(const float* __restrict__ fub,
                                const float* __restrict__ dtb0,
                                const float* __restrict__ dtb1,
                                const float* __restrict__ xpb0,
                                const float* __restrict__ xpb1)
{
    const int i = blockIdx.x * 256 + threadIdx.x;
    if (i < DM)                   g_bpp[i] = fub[i];
    else if (i < DM + DI)         g_b3[0][i - DM] = dtb0[i - DM];
    else if (i < DM + 2 * DI)     g_b3[1][i - DM - DI] = dtb1[i - DM - DI];
    else if (i < DM + 2 * DI + 32)      g_bcb[0][i - DM - 2 * DI] = xpb0[DI + i - DM - 2 * DI];
    else if (i < DM + 2 * DI + 64)      g_bcb[1][i - DM - 2 * DI - 32] = xpb1[DI + i - DM - 2 * DI - 32];
}

// bias partials: z=0 bpp, z=1/2 b3[dir]
__global__ void partials_kernel(const float* __restrict__ fuW,
                                const float* __restrict__ ob0,
                                const float* __restrict__ ob1,
                                const float* __restrict__ dtW0,
                                const float* __restrict__ dtW1,
                                const float* __restrict__ xpb0,
                                const float* __restrict__ xpb1)
{
    const int z = blockIdx.z;
    if (z == 0) {
        if (blockIdx.x >= 4) return;
        const int n = blockIdx.x * 128 + threadIdx.x;
        const int j0 = blockIdx.y * 16;
        float acc = 0.f;
        #pragma unroll
        for (int j = j0; j < j0 + 16; j++) {
            acc += ob0[j] * fuW[(size_t)j * DM + n];
            acc += ob1[j] * fuW[(size_t)(512 + j) * DM + n];
        }
        redg_add(&g_bpp[n], acc);
    } else {
        const int dir = z - 1;
        const float* dtW = dir ? dtW1 : dtW0;
        const float* xpb = dir ? xpb1 : xpb0;
        const int n = blockIdx.x * 128 + threadIdx.x;
        const int j0 = blockIdx.y * 32;
        float acc = 0.f;
        #pragma unroll
        for (int j = j0; j < j0 + 32; j++)
            acc += xpb[j] * dtW[(size_t)j * DI + n];
        redg_add(&g_b3[dir][n], acc);
    }
}

__global__ void initout_kernel(float* __restrict__ out)
{
    const int i = (blockIdx.x * 256 + threadIdx.x) * 4;
    *(float4*)(out + i) = *(const float4*)&g_bpp[i & (DM - 1)];
}

// ------------------------- multi-task ldmatrix tf32 GEMM -------------------
// 256 threads, 8 warps (2x4), warp tile 64x32, CTA tile 128x128, 3 stages.
// epi: 0=none, 1=softplus, 2=round-to-tf32, 3=red.add (no bias)
struct GTask {
    const float *A, *B, *bias; float* C;
    int revA, revC, colOff, lda, ldb, ldc, M, K, k00, epi, nbx;
};
struct GMulti { GTask t[6]; int start[7]; int nt; };

#define TL_STAGE  32768                 // A 16KB + B 16KB (bytes)
#define TL_SMEM   (3 * TL_STAGE)        // 98304

__global__ __launch_bounds__(256, 2)
void tgemm_multi(GMulti gm)
{
    extern __shared__ float smem[];
    const uint32_t sb = smem_u32(smem);
    const int tid = threadIdx.x;
    const int lane = tid & 31;
    const int warp = tid >> 5;
    const int wm = warp & 1;
    const int wn = warp >> 1;
    const int g  = lane >> 2;
    const int cc = lane & 3;

    int ti = 0;
    {
        const int b = blockIdx.x;
        while (ti + 1 < gm.nt && b >= gm.start[ti + 1]) ti++;
    }
    const GTask t = gm.t[ti];
    const int local = blockIdx.x - gm.start[ti];
    const int bx = local % t.nbx;
    const int by = local / t.nbx;

    const float* A = t.A;
    const float* B = t.B;
    const int lda = t.lda, ldb = t.ldb, M = t.M, K = t.K, k00 = t.k00;

    // ---- cp.async mapping: 4 A-chunks + 4 B-chunks of 16B per thread ----
    const int rr = tid >> 3;            // 0..31
    const int kq = tid & 7;             // 0..7
    const float* aBase;
    long aStep;
    {
        long r0 = by * 128 + rr;
        if (t.revA) { aBase = A + (size_t)(M - 1 - r0) * lda; aStep = -32L * lda; }
        else        { aBase = A + (size_t)r0 * lda;           aStep =  32L * lda; }
        aBase += k00 + kq * 4;
    }
    const float* bBase = B + (size_t)(bx * 128 + rr) * ldb + k00 + kq * 4;
    const long bStep = 32L * ldb;
    const uint32_t dA0 = rr * 128 + ((kq * 16) ^ ((rr & 7) * 16));

    auto issue = [&](int k0, int st) {
        const uint32_t base = sb + st * TL_STAGE;
        #pragma unroll
        for (int j = 0; j < 4; j++) cpa16(base + dA0 + j * 4096, aBase + k0 + j * aStep);
        #pragma unroll
        for (int j = 0; j < 4; j++) cpa16(base + 16384 + dA0 + j * 4096, bBase + k0 + j * bStep);
        CPA_COMMIT();
    };

    // ---- ldmatrix lane constants ----
    const uint32_t lxor   = (lane & 7) << 4;
    const uint32_t la_row = (lane & 7) + ((lane >> 3) & 1) * 8;
    const uint32_t la_k16 = (lane >> 4) << 4;
    const uint32_t lb_row = (lane & 7) + ((lane >> 4) << 3);
    const uint32_t lb_k16 = ((lane >> 3) & 1) << 4;
    uint32_t rowAoff[4], rowBoff[2];
    #pragma unroll
    for (int mt = 0; mt < 4; mt++) rowAoff[mt] = (wm * 64 + mt * 16 + la_row) * 128;
    #pragma unroll
    for (int np = 0; np < 2; np++) rowBoff[np] = 16384 + (wn * 32 + np * 16 + lb_row) * 128;

    float acc[4][4][4];
    #pragma unroll
    for (int mt = 0; mt < 4; mt++)
        #pragma unroll
        for (int nt = 0; nt < 4; nt++)
            #pragma unroll
            for (int i = 0; i < 4; i++) acc[mt][nt][i] = 0.f;

    const int nIt = K / 32;
    issue(0, 0);
    issue(32, 1);

    int st = 0, ist = 2;
    for (int it = 0; it < nIt; ++it) {
        if (it + 2 < nIt) { CPA_WAIT(1); } else { CPA_WAIT(0); }
        __syncthreads();
        if (it + 2 < nIt) {
            issue((it + 2) * 32, ist);
            if (++ist == 3) ist = 0;
        }
        const uint32_t stb = sb + st * TL_STAGE;
        if (++st == 3) st = 0;

        #pragma unroll
        for (int ks = 0; ks < 4; ks++) {
            const uint32_t ksb = ks * 32;
            uint32_t a[4][4], b[4][2];
            #pragma unroll
            for (int mt = 0; mt < 4; mt++)
                ldsm4(a[mt], stb + rowAoff[mt] + ((ksb + la_k16) ^ lxor));
            #pragma unroll
            for (int np = 0; np < 2; np++)
                ldsm4(&b[2 * np][0], stb + rowBoff[np] + ((ksb + lb_k16) ^ lxor));
            #pragma unroll
            for (int mt = 0; mt < 4; mt++)
                #pragma unroll
                for (int nt = 0; nt < 4; nt++)
                    mma_tf32(acc[mt][nt], a[mt], b[nt]);
        }
    }

    // ---- epilogue ----
    #pragma unroll
    for (int mt = 0; mt < 4; mt++) {
        int r0 = by * 128 + wm * 64 + mt * 16 + g;
        int r1 = r0 + 8;
        int or0 = t.revC ? (M - 1 - r0) : r0;
        int or1 = t.revC ? (M - 1 - r1) : r1;
        float* crow0 = t.C + (size_t)or0 * t.ldc + t.colOff;
        float* crow1 = t.C + (size_t)or1 * t.ldc + t.colOff;
        #pragma unroll
        for (int nt = 0; nt < 4; nt++) {
            const int col = bx * 128 + wn * 32 + nt * 8 + 2 * cc;
            if (t.epi == 3) {
                redg_add(&crow0[col],     acc[mt][nt][0]);
                redg_add(&crow0[col + 1], acc[mt][nt][1]);
                redg_add(&crow1[col],     acc[mt][nt][2]);
                redg_add(&crow1[col + 1], acc[mt][nt][3]);
            } else {
                float b0 = t.bias[col], b1 = t.bias[col + 1];
                float v00 = acc[mt][nt][0] + b0, v01 = acc[mt][nt][1] + b1;
                float v10 = acc[mt][nt][2] + b0, v11 = acc[mt][nt][3] + b1;
                if (t.epi == 1) {
                    v00 = (v00 > 15.f) ? v00 : log1pf(__expf(v00));
                    v01 = (v01 > 15.f) ? v01 : log1pf(__expf(v01));
                    v10 = (v10 > 15.f) ? v10 : log1pf(__expf(v10));
                    v11 = (v11 > 15.f) ? v11 : log1pf(__expf(v11));
                } else if (t.epi == 2) {
                    v00 = __uint_as_float(f2t(v00)); v01 = __uint_as_float(f2t(v01));
                    v10 = __uint_as_float(f2t(v10)); v11 = __uint_as_float(f2t(v11));
                }
                *(float2*)&crow0[col] = make_float2(v00, v01);
                *(float2*)&crow1[col] = make_float2(v10, v11);
            }
        }
    }
}

// ------------------------- causal depthwise conv (K=4) + silu, float4 ------
__global__ void conv_silu_kernel(const float* __restrict__ cw_f,
                                 const float* __restrict__ cb_f,
                                 const float* __restrict__ cw_b,
                                 const float* __restrict__ cb_b)
{
    const int dir = blockIdx.z;
    const int idx4 = (blockIdx.x * blockDim.x + threadIdx.x) * 4;
    const int l = idx4 >> 10;
    const int d0 = idx4 & (DI - 1);
    const float* xz = g_xz[dir];
    const float* w = dir ? cw_b : cw_f;
    const float* b = dir ? cb_b : cb_f;
    float wk[4][4];
    #pragma unroll
    for (int j = 0; j < 4; j++)
        *(float4*)wk[j] = *(const float4*)&w[(d0 + j) * 4];
    float4 bv = *(const float4*)&b[d0];
    float s[4] = { bv.x, bv.y, bv.z, bv.w };
    #pragma unroll
    for (int k = 0; k < 4; k++) {
        int ls = l - 3 + k;
        if (ls >= 0) {
            float4 xv = *(const float4*)&xz[(size_t)ls * (2 * DI) + d0];
            s[0] += xv.x * wk[0][k];
            s[1] += xv.y * wk[1][k];
            s[2] += xv.z * wk[2][k];
            s[3] += xv.w * wk[3][k];
        }
    }
    *(float4*)&g_xc[dir][idx4] = make_float4(s[0], s[1], s[2], s[3]);
    float4 o;
    o.x = __uint_as_float(f2t(s[0] / (1.f + __expf(-s[0]))));
    o.y = __uint_as_float(f2t(s[1] / (1.f + __expf(-s[1]))));
    o.z = __uint_as_float(f2t(s[2] / (1.f + __expf(-s[2]))));
    o.w = __uint_as_float(f2t(s[3] / (1.f + __expf(-s[3]))));
    *(float4*)&g_sxc[dir][idx4] = o;
}

// ------------------------- chunked scan (s-in-thread, 2 ch/thread) ---------
#define LOG2E 1.44269504088896f

__global__ __launch_bounds__(256)
void scan_phaseA(const float* __restrict__ A_log)
{
    __shared__ float sB[TCH][16];
    const int dir = blockIdx.z;
    const int c = blockIdx.x;
    const int d0 = blockIdx.y * 512 + threadIdx.x * 2;
    const float* bc = g_BCp[dir];
    for (int i = threadIdx.x; i < TCH * 16; i += 256) {
        const int t = i >> 4, s = i & 15;
        sB[t][s] = bc[(c * TCH + t) * 128 + s];
    }
    __syncthreads();

    float2 Av[NST];
    #pragma unroll
    for (int q = 0; q < 4; q++) {
        float4 v0 = *(const float4*)&A_log[d0 * NST + q * 4];
        float4 v1 = *(const float4*)&A_log[(d0 + 1) * NST + q * 4];
        Av[q * 4 + 0] = make_float2(-__expf(v0.x) * LOG2E, -__expf(v1.x) * LOG2E);
        Av[q * 4 + 1] = make_float2(-__expf(v0.y) * LOG2E, -__expf(v1.y) * LOG2E);
        Av[q * 4 + 2] = make_float2(-__expf(v0.z) * LOG2E, -__expf(v1.z) * LOG2E);
        Av[q * 4 + 3] = make_float2(-__expf(v0.w) * LOG2E, -__expf(v1.w) * LOG2E);
    }
    float2 h[NST], ap[NST];
    #pragma unroll
    for (int s = 0; s < NST; s++) {
        h[s] = make_float2(0.f, 0.f);
        ap[s] = make_float2(1.f, 1.f);
    }

    const float* dtp = g_dt[dir];
    const float* xp = g_xc[dir];
    int l = c * TCH;
    for (int t = 0; t < TCH; t++, l++) {
        const float2 dtv = *(const float2*)&dtp[l * DI + d0];
        const float2 xv  = *(const float2*)&xp[l * DI + d0];
        const float dtx0 = dtv.x * xv.x, dtx1 = dtv.y * xv.y;
        #pragma unroll
        for (int s = 0; s < NST; s++) {
            const float a0 = exp2f(dtv.x * Av[s].x);
            const float a1 = exp2f(dtv.y * Av[s].y);
            const float Bs = sB[t][s];
            h[s].x = a0 * h[s].x + dtx0 * Bs;
            h[s].y = a1 * h[s].y + dtx1 * Bs;
            ap[s].x *= a0; ap[s].y *= a1;
        }
    }
    const int ob = (c << 14) + d0;
    #pragma unroll
    for (int s = 0; s < NST; s++) {
        *(float2*)&g_aprod[dir][ob + (s << 10)] = ap[s];
        *(float2*)&g_hpart[dir][ob + (s << 10)] = h[s];
    }
}

__global__ void scan_phaseB()
{
    const int idx = blockIdx.x * blockDim.x + threadIdx.x;
    const int dir = idx >> 14;
    const int ds = idx & 16383;
    float h = 0.f;
    float ap = g_aprod[dir][ds];
    float hp = g_hpart[dir][ds];
    for (int c = 0; c < NC; c++) {
        float apn = 0.f, hpn = 0.f;
        if (c + 1 < NC) {
            const int on = ((c + 1) << 14) + ds;
            apn = g_aprod[dir][on];
            hpn = g_hpart[dir][on];
        }
        g_hinit[dir][(c << 14) + ds] = h;
        h = ap * h + hp;
        ap = apn; hp = hpn;
    }
}

__global__ __launch_bounds__(256)
void scan_phaseC(const float* __restrict__ A_log,
                 const float* __restrict__ Dp)
{
    __shared__ float sBC[TCH][32];
    const int dir = blockIdx.z;
    const int c = blockIdx.x;
    const int d0 = blockIdx.y * 512 + threadIdx.x * 2;
    const float* bc = g_BCp[dir];
    for (int i = threadIdx.x; i < TCH * 32; i += 256) {
        const int t = i >> 5, s = i & 31;
        sBC[t][s] = bc[(c * TCH + t) * 128 + s];
    }
    __syncthreads();

    float2 Av[NST];
    #pragma unroll
    for (int q = 0; q < 4; q++) {
        float4 v0 = *(const float4*)&A_log[d0 * NST + q * 4];
        float4 v1 = *(const float4*)&A_log[(d0 + 1) * NST + q * 4];
        Av[q * 4 + 0] = make_float2(-__expf(v0.x) * LOG2E, -__expf(v1.x) * LOG2E);
        Av[q * 4 + 1] = make_float2(-__expf(v0.y) * LOG2E, -__expf(v1.y) * LOG2E);
        Av[q * 4 + 2] = make_float2(-__expf(v0.z) * LOG2E, -__expf(v1.z) * LOG2E);
        Av[q * 4 + 3] = make_float2(-__expf(v0.w) * LOG2E, -__expf(v1.w) * LOG2E);
    }
    const float2 Dv = *(const float2*)&Dp[d0];
    float2 h[NST];
    {
        const int ob = (c << 14) + d0;
        #pragma unroll
        for (int s = 0; s < NST; s++)
            h[s] = *(const float2*)&g_hinit[dir][ob + (s << 10)];
    }

    const float* dtp = g_dt[dir];
    const float* xp = g_xc[dir];
    const float* xz = g_xz[dir];
    int l = c * TCH;
    for (int t = 0; t < TCH; t++, l++) {
        const float2 dtv = *(const float2*)&dtp[l * DI + d0];
        const float2 xv  = *(const float2*)&xp[l * DI + d0];
        const float2 zv  = *(const float2*)&xz[(size_t)l * (2 * DI) + DI + d0];
        const float dtx0 = dtv.x * xv.x, dtx1 = dtv.y * xv.y;
        float y0 = Dv.x * xv.x, y1 = Dv.y * xv.y;
        #pragma unroll
        for (int s = 0; s < NST; s++) {
            const float a0 = exp2f(dtv.x * Av[s].x);
            const float a1 = exp2f(dtv.y * Av[s].y);
            const float Bs = sBC[t][s];
            const float Cs = sBC[t][16 + s];
            h[s].x = a0 * h[s].x + dtx0 * Bs;
            h[s].y = a1 * h[s].y + dtx1 * Bs;
            y0 += h[s].x * Cs;
            y1 += h[s].y * Cs;
        }
        const float u0 = y0 * (zv.x / (1.f + __expf(-zv.x)));
        const float u1 = y1 * (zv.y / (1.f + __expf(-zv.y)));
        const size_t row = dir ? (size_t)(L - 1 - l) : (size_t)l;
        float2 uo = make_float2(__uint_as_float(f2t(u0)), __uint_as_float(f2t(u1)));
        *(float2*)&g_uu[row * (2 * DI) + dir * DI + d0] = uo;
    }
}

// ------------------------- host launcher --------------------------------
extern "C" void kernel_launch(void* const* d_in, const int* in_sizes, int n_in,
                              void* d_out, int out_size)
{
    (void)in_sizes; (void)n_in; (void)out_size;
    const float* x = (const float*)d_in[0];
    const float* inW[2]  = { (const float*)d_in[1],  (const float*)d_in[11] };
    const float* inb[2]  = { (const float*)d_in[2],  (const float*)d_in[12] };
    const float* cw[2]   = { (const float*)d_in[3],  (const float*)d_in[13] };
    const float* cb[2]   = { (const float*)d_in[4],  (const float*)d_in[14] };
    const float* xpW[2]  = { (const float*)d_in[5],  (const float*)d_in[15] };
    const float* xpb[2]  = { (const float*)d_in[6],  (const float*)d_in[16] };
    const float* dtW[2]  = { (const float*)d_in[7],  (const float*)d_in[17] };
    const float* dtb[2]  = { (const float*)d_in[8],  (const float*)d_in[18] };
    const float* outW[2] = { (const float*)d_in[9],  (const float*)d_in[19] };
    const float* outb[2] = { (const float*)d_in[10], (const float*)d_in[20] };
    const float* A_log   = (const float*)d_in[21];
    const float* Dp      = (const float*)d_in[22];
    const float* fuW     = (const float*)d_in[23];
    const float* fub     = (const float*)d_in[24];
    float* out = (float*)d_out;

    float *xz, *uu, *wr, *sxc, *dtbuf, *wpp, *w3, *b3, *zero, *bcp, *bcb;
    cudaGetSymbolAddress((void**)&xz,    g_xz);
    cudaGetSymbolAddress((void**)&uu,    g_uu);
    cudaGetSymbolAddress((void**)&wr,    g_wr);
    cudaGetSymbolAddress((void**)&sxc,   g_sxc);
    cudaGetSymbolAddress((void**)&dtbuf, g_dt);
    cudaGetSymbolAddress((void**)&wpp,   g_wpp);
    cudaGetSymbolAddress((void**)&w3,    g_w3);
    cudaGetSymbolAddress((void**)&b3,    g_b3);
    cudaGetSymbolAddress((void**)&zero,  g_zero);
    cudaGetSymbolAddress((void**)&bcp,   g_BCp);
    cudaGetSymbolAddress((void**)&bcb,   g_bcb);

    cudaFuncSetAttribute(tgemm_multi, cudaFuncAttributeMaxDynamicSharedMemorySize, TL_SMEM);

    const dim3 blk(256);

    // side stream + fork/join events
    cudaStream_t side;
    cudaStreamCreateWithFlags(&side, cudaStreamNonBlocking);
    cudaEvent_t evFork, evPrep, evJoin1, evJoin2;
    cudaEventCreateWithFlags(&evFork,  cudaEventDisableTiming);
    cudaEventCreateWithFlags(&evPrep,  cudaEventDisableTiming);
    cudaEventCreateWithFlags(&evJoin1, cudaEventDisableTiming);
    cudaEventCreateWithFlags(&evJoin2, cudaEventDisableTiming);

    cudaEventRecord(evFork, 0);
    cudaStreamWaitEvent(side, evFork, 0);

    // ---- side branch: bias chain (independent of prep/mega1/conv) ----
    biascopy_kernel<<<11, blk, 0, side>>>(fub, dtb[0], dtb[1], xpb[0], xpb[1]);
    partials_kernel<<<dim3(8, 32, 3), 128, 0, side>>>(fuW, outb[0], outb[1],
                                                      dtW[0], dtW[1], xpb[0], xpb[1]);
    initout_kernel<<<L * DM / 4 / 256, blk, 0, side>>>(out);
    cudaEventRecord(evJoin1, side);

    // ---- main branch ----
    // 1. prep: weight transposes (rounded)
    {
        PrepArgs pa{};
        pa.ts[0] = inW[0]; pa.td[0] = wr + OFF_INWT0;  pa.tK[0] = DM;     pa.tN[0] = 2 * DI; pa.tld[0] = 2 * DI; pa.tcoff[0] = 0;
        pa.ts[1] = inW[1]; pa.td[1] = wr + OFF_INWT1;  pa.tK[1] = DM;     pa.tN[1] = 2 * DI; pa.tld[1] = 2 * DI; pa.tcoff[1] = 0;
        pa.ts[2] = dtW[0]; pa.td[2] = wr + OFF_DTWT0;  pa.tK[2] = DI;     pa.tN[2] = DI;     pa.tld[2] = DI;     pa.tcoff[2] = 0;
        pa.ts[3] = dtW[1]; pa.td[3] = wr + OFF_DTWT1;  pa.tK[3] = DI;     pa.tN[3] = DI;     pa.tld[3] = DI;     pa.tcoff[3] = 0;
        pa.ts[4] = fuW;    pa.td[4] = wr + OFF_FUWT;   pa.tK[4] = 2 * DM; pa.tN[4] = DM;     pa.tld[4] = DM;     pa.tcoff[4] = 0;
        pa.ts[5] = xpW[0]; pa.td[5] = wr + OFF_XPBCT0; pa.tK[5] = DI;     pa.tN[5] = 32;     pa.tld[5] = 1056;   pa.tcoff[5] = DI;
        pa.ts[6] = xpW[1]; pa.td[6] = wr + OFF_XPBCT1; pa.tK[6] = DI;     pa.tN[6] = 32;     pa.tld[6] = 1056;   pa.tcoff[6] = DI;
        prep_kernel<<<dim3(1024, 1, 7), blk>>>(pa);
    }
    cudaEventRecord(evPrep, 0);

    // ---- side branch (cont.): Wpp compose GEMM, needs prep's FUWT ----
    cudaStreamWaitEvent(side, evPrep, 0);
    {
        GMulti gm{};
        int s = 0, i = 0;
        for (int d2 = 0; d2 < 2; d2++) {   // Wpp compose
            gm.t[i] = { wr + OFF_FUWT + d2 * 512, outW[d2], zero,
                        wpp,
                        0, 0, d2 * DI, 2 * DM, DM, 2 * DI, DM, DM, 0, 2, 8 };
            gm.start[i] = s; s += 8 * 4; i++;
        }
        gm.start[i] = s; gm.nt = i;
        tgemm_multi<<<s, blk, TL_SMEM, side>>>(gm);
    }
    cudaEventRecord(evJoin2, side);

    // 2. mega1: W3 x2 (long K first) + in-proj x2
    {
        GMulti gm{};
        int s = 0, i = 0;
        for (int d2 = 0; d2 < 2; d2++) {   // W3 compose (K=1056)
            gm.t[i] = { wr + (d2 ? OFF_DTWT1 : OFF_DTWT0), xpW[d2], zero,
                        w3 + (size_t)d2 * DI * DI,
                        0, 0, 0, DI, 1056, DI, DI, DI, 0, 2, 8 };
            gm.start[i] = s; s += 8 * 8; i++;
        }
        for (int d2 = 0; d2 < 2; d2++) {   // in-proj (K=512)
            gm.t[i] = { x, wr + (d2 ? OFF_INWT1 : OFF_INWT0), inb[d2],
                        xz + (size_t)d2 * L * 2 * DI,
                        d2, 0, 0, DM, DM, 2 * DI, L, DM, 0, 0, 16 };
            gm.start[i] = s; s += 16 * 16; i++;
        }
        gm.start[i] = s; gm.nt = i;
        tgemm_multi<<<s, blk, TL_SMEM>>>(gm);
    }

    // 3. causal conv + silu
    conv_silu_kernel<<<dim3(L * DI / 1024, 1, 2), blk>>>(cw[0], cb[0], cw[1], cb[1]);

    // join1: mega2 needs b3/bcb
    cudaStreamWaitEvent(0, evJoin1, 0);

    // 4. mega2: dt x2 + BC x2
    {
        GMulti gm{};
        int s = 0, i = 0;
        for (int d2 = 0; d2 < 2; d2++) {   // dt = softplus(sxc @ W3 + b3)
            gm.t[i] = { sxc + (size_t)d2 * L * DI, w3 + (size_t)d2 * DI * DI, b3 + d2 * DI,
                        dtbuf + (size_t)d2 * L * DI,
                        0, 0, 0, DI, DI, DI, L, DI, 0, 1, 8 };
            gm.start[i] = s; s += 8 * 16; i++;
        }
        for (int d2 = 0; d2 < 2; d2++) {   // BC projection (padded N=128)
            gm.t[i] = { sxc + (size_t)d2 * L * DI, wr + (d2 ? OFF_XPBCT1 : OFF_XPBCT0), bcb + d2 * 128,
                        bcp + (size_t)d2 * L * 128,
                        0, 0, 0, DI, DI, 128, L, DI, 0, 0, 1 };
            gm.start[i] = s; s += 1 * 16; i++;
        }
        gm.start[i] = s; gm.nt = i;
        tgemm_multi<<<s, blk, TL_SMEM>>>(gm);
    }

    // 5. chunked selective scan -> uu  (2 channels/thread)
    scan_phaseA<<<dim3(NC, DI / 512, 2), blk>>>(A_log);
    scan_phaseB<<<2 * DI * NST / 256, blk>>>();
    scan_phaseC<<<dim3(NC, DI / 512, 2), blk>>>(A_log, Dp);

    // join2: mega3 needs wpp + out-init
    cudaStreamWaitEvent(0, evJoin2, 0);

    // 6. mega3: final fused GEMM out += uu @ W''^T  (split-K=4 via tasks;
    //    256 CTAs = single wave, each CTA half the K-iters of split-K=2)
    {
        GMulti gm{};
        int s = 0, i = 0;
        for (int kz = 0; kz < 4; kz++) {
            gm.t[i] = { uu, wpp, zero, out,
                        0, 0, 0, 2 * DI, 2 * DI, DM, L, 512, kz * 512, 3, 4 };
            gm.start[i] = s; s += 4 * 16; i++;
        }
        gm.start[i] = s; gm.nt = i;
        tgemm_multi<<<s, blk, TL_SMEM>>>(gm);
    }
}